// round 4
// baseline (speedup 1.0000x reference)
#include <cuda_runtime.h>
#include <cuda_bf16.h>
#include <cstdint>
#include <cstddef>

// ---------------- problem constants ----------------
#define BATCH   16384
#define DMODEL  1024
#define PHYSD   11
#define NTOK    4
#define NHEAD   4
#define DHEAD   256           // DMODEL / NHEAD
#define DN      4096          // DMODEL * NTOK
#define LN_EPS  1e-5f

// ---------------- device scratch (allocation-free rule) ----------------
__device__ float g_h      [(size_t)BATCH * DN];      // gelu(physics@pw1+pb1)
__device__ float g_physkv [(size_t)BATCH * DN];      // h@pw2+pb2
__device__ float g_kvln   [(size_t)BATCH * DN];      // LN(physkv) as [B*NT, D]
__device__ float g_qln    [(size_t)BATCH * DMODEL];  // LN(embedding)
__device__ float g_qproj  [(size_t)BATCH * DMODEL];  // q@wq+bq
__device__ float g_k      [(size_t)BATCH * DN];      // kvln@wk+bk   [B*NT, D]
__device__ float g_v      [(size_t)BATCH * DN];      // kvln@wv+bv   [B*NT, D]
__device__ float g_ctx    [(size_t)BATCH * DMODEL];  // attention context
__device__ float g_fused  [(size_t)BATCH * DMODEL];  // embedding + sig*attn_out
__device__ float g_fusedln[(size_t)BATCH * DMODEL];  // LN(fused)
__device__ float g_ffh    [(size_t)BATCH * 2048];    // gelu(.@fw1+fb1)

// ---------------- helpers ----------------
__device__ __forceinline__ float gelu_f(float x) {
    // jax.nn.gelu default = tanh approximation
    float x3 = x * x * x;
    float t  = tanhf(0.79788456080286535588f * (x + 0.044715f * x3));
    return 0.5f * x * (1.0f + t);
}

__device__ __forceinline__ float tf32r(float x) {
    uint32_t u;
    asm volatile("cvt.rna.tf32.f32 %0, %1;" : "=r"(u) : "f"(x));
    return __uint_as_float(u);
}

// ================= tf32 GEMM: out[M,N] = A[M,K] @ W[K,N] + bias, epilogue =================
// BM=128 BN=128 BK=32, 256 threads = 8 warps (2 M x 4 N), warp tile 64x32.
// mma.sync.aligned.m16n8k8.row.col.f32.tf32.tf32.f32
enum { EPI_STORE = 0, EPI_GELU = 1, EPI_FUSED = 2, EPI_ADDOUT = 3 };

template <int EPI>
__global__ __launch_bounds__(256)
void gemm_tf32(const float* __restrict__ A, const float* __restrict__ W,
               const float* __restrict__ bias, float* __restrict__ out,
               const float* __restrict__ aux, const float* __restrict__ gatep,
               int M, int N, int K)
{
    __shared__ float As[128][36];   // pad 36: frag banks (4g+c)%32 distinct
    __shared__ float Bs[32][136];   // pad 136: frag banks (8c+g)%32 distinct

    const int tid  = threadIdx.x;
    const int lane = tid & 31;
    const int wid  = tid >> 5;
    const int wm   = wid >> 2;          // 0..1
    const int wn   = wid & 3;           // 0..3
    const int g    = lane >> 2;         // 0..7
    const int c    = lane & 3;          // 0..3
    const int bm0  = blockIdx.y * 128;
    const int bn0  = blockIdx.x * 128;

    // staging index maps
    const int arow = tid >> 3;          // 0..31 (+32*i)
    const int ac4  = tid & 7;           // 0..7
    const int brow = tid >> 5;          // 0..7  (+8*i)
    const int bc4  = tid & 31;          // 0..31

    float acc[4][4][4];
#pragma unroll
    for (int mi = 0; mi < 4; mi++)
#pragma unroll
        for (int ni = 0; ni < 4; ni++)
#pragma unroll
            for (int e = 0; e < 4; e++) acc[mi][ni][e] = 0.f;

    const int ntiles = K >> 5;
    float4 aReg[4], bReg[4];

    // ---- load tile 0 into regs ----
#pragma unroll
    for (int i = 0; i < 4; i++)
        aReg[i] = *(const float4*)(A + (size_t)(bm0 + arow + 32 * i) * K + ac4 * 4);
#pragma unroll
    for (int i = 0; i < 4; i++)
        bReg[i] = *(const float4*)(W + (size_t)(brow + 8 * i) * N + bn0 + bc4 * 4);

    // ---- store tile 0 (tf32-rounded) ----
#pragma unroll
    for (int i = 0; i < 4; i++) {
        float4 t = aReg[i];
        float4 s = make_float4(tf32r(t.x), tf32r(t.y), tf32r(t.z), tf32r(t.w));
        *(float4*)&As[arow + 32 * i][ac4 * 4] = s;
    }
#pragma unroll
    for (int i = 0; i < 4; i++) {
        float4 t = bReg[i];
        float4 s = make_float4(tf32r(t.x), tf32r(t.y), tf32r(t.z), tf32r(t.w));
        *(float4*)&Bs[brow + 8 * i][bc4 * 4] = s;
    }
    __syncthreads();

    for (int kt = 0; kt < ntiles; kt++) {
        const bool has_next = (kt + 1 < ntiles);
        if (has_next) {
            const int k0 = (kt + 1) * 32;
#pragma unroll
            for (int i = 0; i < 4; i++)
                aReg[i] = *(const float4*)(A + (size_t)(bm0 + arow + 32 * i) * K + k0 + ac4 * 4);
#pragma unroll
            for (int i = 0; i < 4; i++)
                bReg[i] = *(const float4*)(W + (size_t)(k0 + brow + 8 * i) * N + bn0 + bc4 * 4);
        }

        // ---- compute current tile ----
#pragma unroll
        for (int ks = 0; ks < 4; ks++) {
            uint32_t af[4][4], bf[4][2];
#pragma unroll
            for (int mi = 0; mi < 4; mi++) {
                int r = wm * 64 + mi * 16 + g;
                af[mi][0] = __float_as_uint(As[r    ][ks * 8 + c]);
                af[mi][1] = __float_as_uint(As[r + 8][ks * 8 + c]);
                af[mi][2] = __float_as_uint(As[r    ][ks * 8 + c + 4]);
                af[mi][3] = __float_as_uint(As[r + 8][ks * 8 + c + 4]);
            }
#pragma unroll
            for (int ni = 0; ni < 4; ni++) {
                int col = wn * 32 + ni * 8 + g;
                bf[ni][0] = __float_as_uint(Bs[ks * 8 + c    ][col]);
                bf[ni][1] = __float_as_uint(Bs[ks * 8 + c + 4][col]);
            }
#pragma unroll
            for (int mi = 0; mi < 4; mi++)
#pragma unroll
                for (int ni = 0; ni < 4; ni++) {
                    asm volatile(
                        "mma.sync.aligned.m16n8k8.row.col.f32.tf32.tf32.f32 "
                        "{%0,%1,%2,%3}, {%4,%5,%6,%7}, {%8,%9}, {%0,%1,%2,%3};\n"
                        : "+f"(acc[mi][ni][0]), "+f"(acc[mi][ni][1]),
                          "+f"(acc[mi][ni][2]), "+f"(acc[mi][ni][3])
                        : "r"(af[mi][0]), "r"(af[mi][1]), "r"(af[mi][2]), "r"(af[mi][3]),
                          "r"(bf[ni][0]), "r"(bf[ni][1]));
                }
        }
        __syncthreads();

        if (has_next) {
#pragma unroll
            for (int i = 0; i < 4; i++) {
                float4 t = aReg[i];
                float4 s = make_float4(tf32r(t.x), tf32r(t.y), tf32r(t.z), tf32r(t.w));
                *(float4*)&As[arow + 32 * i][ac4 * 4] = s;
            }
#pragma unroll
            for (int i = 0; i < 4; i++) {
                float4 t = bReg[i];
                float4 s = make_float4(tf32r(t.x), tf32r(t.y), tf32r(t.z), tf32r(t.w));
                *(float4*)&Bs[brow + 8 * i][bc4 * 4] = s;
            }
        }
        __syncthreads();
    }

    // ---- epilogue ----
    float sig = 1.f;
    if (EPI == EPI_FUSED) sig = 1.f / (1.f + expf(-gatep[0]));

#pragma unroll
    for (int mi = 0; mi < 4; mi++) {
#pragma unroll
        for (int ni = 0; ni < 4; ni++) {
            int r0  = bm0 + wm * 64 + mi * 16 + g;
            int col = bn0 + wn * 32 + ni * 8 + 2 * c;
            float bv0 = bias[col], bv1 = bias[col + 1];
#pragma unroll
            for (int half = 0; half < 2; half++) {
                int r = r0 + half * 8;
                size_t i0 = (size_t)r * N + col;
                float v0 = acc[mi][ni][half * 2 + 0] + bv0;
                float v1 = acc[mi][ni][half * 2 + 1] + bv1;
                if (EPI == EPI_STORE) {
                    out[i0] = v0; out[i0 + 1] = v1;
                } else if (EPI == EPI_GELU) {
                    out[i0] = gelu_f(v0); out[i0 + 1] = gelu_f(v1);
                } else if (EPI == EPI_FUSED) {
                    out[i0]     = aux[i0]     + sig * v0;
                    out[i0 + 1] = aux[i0 + 1] + sig * v1;
                } else { // EPI_ADDOUT
                    out[i0]     = aux[i0]     + v0;
                    out[i0 + 1] = aux[i0 + 1] + v1;
                }
            }
        }
    }
}

// ================= phys MLP stage 1: gelu(physics @ pw1 + pb1) =================
__global__ __launch_bounds__(256)
void phys_mlp1(const float* __restrict__ phys, const float* __restrict__ pw1,
               const float* __restrict__ pb1, float* __restrict__ out)
{
    __shared__ float p[PHYSD];
    int b = blockIdx.x;
    int tid = threadIdx.x;
    if (tid < PHYSD) p[tid] = phys[(size_t)b * PHYSD + tid];
    __syncthreads();
    float pr[PHYSD];
#pragma unroll
    for (int k = 0; k < PHYSD; k++) pr[k] = p[k];
    for (int n = tid; n < DN; n += 256) {
        float s = pb1[n];
#pragma unroll
        for (int k = 0; k < PHYSD; k++) s = fmaf(pr[k], pw1[(size_t)k * DN + n], s);
        out[(size_t)b * DN + n] = gelu_f(s);
    }
}

// ================= LayerNorm over D=1024, block per row =================
__global__ __launch_bounds__(256)
void ln1024(const float* __restrict__ x, const float* __restrict__ gg,
            const float* __restrict__ bb, float* __restrict__ out)
{
    __shared__ float red1[8], red2[8];
    int row = blockIdx.x;
    int tid = threadIdx.x;
    int lane = tid & 31, wid = tid >> 5;

    float4 v = *(const float4*)(x + (size_t)row * DMODEL + tid * 4);
    float s1 = v.x + v.y + v.z + v.w;
    float s2 = v.x * v.x + v.y * v.y + v.z * v.z + v.w * v.w;
#pragma unroll
    for (int o = 16; o > 0; o >>= 1) {
        s1 += __shfl_down_sync(0xFFFFFFFFu, s1, o);
        s2 += __shfl_down_sync(0xFFFFFFFFu, s2, o);
    }
    if (lane == 0) { red1[wid] = s1; red2[wid] = s2; }
    __syncthreads();
    if (tid == 0) {
        float a = 0.f, b2 = 0.f;
#pragma unroll
        for (int i = 0; i < 8; i++) { a += red1[i]; b2 += red2[i]; }
        red1[0] = a; red2[0] = b2;
    }
    __syncthreads();
    float mu  = red1[0] * (1.f / DMODEL);
    float var = red2[0] * (1.f / DMODEL) - mu * mu;
    float rs  = rsqrtf(var + LN_EPS);

    float4 gv = *(const float4*)(gg + tid * 4);
    float4 bv = *(const float4*)(bb + tid * 4);
    float4 o;
    o.x = (v.x - mu) * rs * gv.x + bv.x;
    o.y = (v.y - mu) * rs * gv.y + bv.y;
    o.z = (v.z - mu) * rs * gv.z + bv.z;
    o.w = (v.w - mu) * rs * gv.w + bv.w;
    *(float4*)(out + (size_t)row * DMODEL + tid * 4) = o;
}

// ================= attention: warp per (b, head), NT=4, DH=256 =================
__device__ __forceinline__ float dot4(float4 a, float4 b) {
    return fmaf(a.x, b.x, fmaf(a.y, b.y, fmaf(a.z, b.z, a.w * b.w)));
}

__global__ __launch_bounds__(256)
void attn_kernel(const float* __restrict__ q, const float* __restrict__ k,
                 const float* __restrict__ v, float* __restrict__ ctx)
{
    int warp = (blockIdx.x * 256 + threadIdx.x) >> 5;
    int lane = threadIdx.x & 31;
    int b = warp >> 2, h = warp & 3;

    size_t qoff = (size_t)b * DMODEL + h * DHEAD;
    float4 q0 = *(const float4*)(q + qoff + lane * 4);
    float4 q1 = *(const float4*)(q + qoff + 128 + lane * 4);

    float s[NTOK];
#pragma unroll
    for (int t = 0; t < NTOK; t++) {
        size_t koff = (size_t)(b * NTOK + t) * DMODEL + h * DHEAD;
        float4 k0 = *(const float4*)(k + koff + lane * 4);
        float4 k1 = *(const float4*)(k + koff + 128 + lane * 4);
        float d = dot4(q0, k0) + dot4(q1, k1);
#pragma unroll
        for (int o = 16; o > 0; o >>= 1) d += __shfl_xor_sync(0xFFFFFFFFu, d, o);
        s[t] = d * (1.f / 16.f);   // 1/sqrt(256)
    }
    float m = fmaxf(fmaxf(s[0], s[1]), fmaxf(s[2], s[3]));
    float e[NTOK], sum = 0.f;
#pragma unroll
    for (int t = 0; t < NTOK; t++) { e[t] = expf(s[t] - m); sum += e[t]; }
    float inv = 1.f / sum;

    float4 c0 = make_float4(0.f, 0.f, 0.f, 0.f);
    float4 c1 = make_float4(0.f, 0.f, 0.f, 0.f);
#pragma unroll
    for (int t = 0; t < NTOK; t++) {
        float a = e[t] * inv;
        size_t voff = (size_t)(b * NTOK + t) * DMODEL + h * DHEAD;
        float4 v0 = *(const float4*)(v + voff + lane * 4);
        float4 v1 = *(const float4*)(v + voff + 128 + lane * 4);
        c0.x = fmaf(a, v0.x, c0.x); c0.y = fmaf(a, v0.y, c0.y);
        c0.z = fmaf(a, v0.z, c0.z); c0.w = fmaf(a, v0.w, c0.w);
        c1.x = fmaf(a, v1.x, c1.x); c1.y = fmaf(a, v1.y, c1.y);
        c1.z = fmaf(a, v1.z, c1.z); c1.w = fmaf(a, v1.w, c1.w);
    }
    *(float4*)(ctx + qoff + lane * 4) = c0;
    *(float4*)(ctx + qoff + 128 + lane * 4) = c1;
}

// ================= host launcher =================
extern "C" void kernel_launch(void* const* d_in, const int* in_sizes, int n_in,
                              void* d_out, int out_size)
{
    const float* embedding = (const float*)d_in[0];
    const float* physics   = (const float*)d_in[1];
    const float* pw1   = (const float*)d_in[2];
    const float* pb1   = (const float*)d_in[3];
    const float* pw2   = (const float*)d_in[4];
    const float* pb2   = (const float*)d_in[5];
    const float* lnq_g = (const float*)d_in[6];
    const float* lnq_b = (const float*)d_in[7];
    const float* lnkv_g = (const float*)d_in[8];
    const float* lnkv_b = (const float*)d_in[9];
    const float* wq = (const float*)d_in[10];
    const float* bq = (const float*)d_in[11];
    const float* wk = (const float*)d_in[12];
    const float* bk = (const float*)d_in[13];
    const float* wv = (const float*)d_in[14];
    const float* bv = (const float*)d_in[15];
    const float* wo = (const float*)d_in[16];
    const float* bo = (const float*)d_in[17];
    const float* ffn_g = (const float*)d_in[18];
    const float* ffn_b = (const float*)d_in[19];
    const float* fw1 = (const float*)d_in[20];
    const float* fb1 = (const float*)d_in[21];
    const float* fw2 = (const float*)d_in[22];
    const float* fb2 = (const float*)d_in[23];
    const float* gate = (const float*)d_in[24];
    float* out = (float*)d_out;

    float *p_h, *p_physkv, *p_kvln, *p_qln, *p_qproj, *p_k, *p_v,
          *p_ctx, *p_fused, *p_fusedln, *p_ffh;
    cudaGetSymbolAddress((void**)&p_h, g_h);
    cudaGetSymbolAddress((void**)&p_physkv, g_physkv);
    cudaGetSymbolAddress((void**)&p_kvln, g_kvln);
    cudaGetSymbolAddress((void**)&p_qln, g_qln);
    cudaGetSymbolAddress((void**)&p_qproj, g_qproj);
    cudaGetSymbolAddress((void**)&p_k, g_k);
    cudaGetSymbolAddress((void**)&p_v, g_v);
    cudaGetSymbolAddress((void**)&p_ctx, g_ctx);
    cudaGetSymbolAddress((void**)&p_fused, g_fused);
    cudaGetSymbolAddress((void**)&p_fusedln, g_fusedln);
    cudaGetSymbolAddress((void**)&p_ffh, g_ffh);

    // 1) h = gelu(physics @ pw1 + pb1)
    phys_mlp1<<<BATCH, 256>>>(physics, pw1, pb1, p_h);

    // 2) physkv = h @ pw2 + pb2    [16384, 4096] x [4096, 4096]
    gemm_tf32<EPI_STORE><<<dim3(DN / 128, BATCH / 128), 256>>>(
        p_h, pw2, pb2, p_physkv, nullptr, nullptr, BATCH, DN, DN);

    // 3) LayerNorms
    ln1024<<<BATCH * NTOK, 256>>>(p_physkv, lnkv_g, lnkv_b, p_kvln);
    ln1024<<<BATCH, 256>>>(embedding, lnq_g, lnq_b, p_qln);

    // 4) projections
    gemm_tf32<EPI_STORE><<<dim3(DMODEL / 128, BATCH / 128), 256>>>(
        p_qln, wq, bq, p_qproj, nullptr, nullptr, BATCH, DMODEL, DMODEL);
    gemm_tf32<EPI_STORE><<<dim3(DMODEL / 128, (BATCH * NTOK) / 128), 256>>>(
        p_kvln, wk, bk, p_k, nullptr, nullptr, BATCH * NTOK, DMODEL, DMODEL);
    gemm_tf32<EPI_STORE><<<dim3(DMODEL / 128, (BATCH * NTOK) / 128), 256>>>(
        p_kvln, wv, bv, p_v, nullptr, nullptr, BATCH * NTOK, DMODEL, DMODEL);

    // 5) attention (warp per (b, head))
    attn_kernel<<<(BATCH * NHEAD) / 8, 256>>>(p_qproj, p_k, p_v, p_ctx);

    // 6) fused = embedding + sigmoid(gate) * (ctx @ wo + bo)
    gemm_tf32<EPI_FUSED><<<dim3(DMODEL / 128, BATCH / 128), 256>>>(
        p_ctx, wo, bo, p_fused, embedding, gate, BATCH, DMODEL, DMODEL);

    // 7) LN(fused)
    ln1024<<<BATCH, 256>>>(p_fused, ffn_g, ffn_b, p_fusedln);

    // 8) ffh = gelu(fusedln @ fw1 + fb1)   [16384, 1024] x [1024, 2048]
    gemm_tf32<EPI_GELU><<<dim3(2048 / 128, BATCH / 128), 256>>>(
        p_fusedln, fw1, fb1, p_ffh, nullptr, nullptr, BATCH, 2048, DMODEL);

    // 9) out = fused + ffh @ fw2 + fb2     [16384, 2048] x [2048, 1024]
    gemm_tf32<EPI_ADDOUT><<<dim3(DMODEL / 128, BATCH / 128), 256>>>(
        p_ffh, fw2, fb2, out, p_fused, nullptr, BATCH, DMODEL, 2048);
}

// round 6
// speedup vs baseline: 2.0758x; 2.0758x over previous
#include <cuda_runtime.h>
#include <cuda_fp16.h>
#include <cstdint>
#include <cstddef>

// ---------------- problem constants ----------------
#define BATCH   16384
#define DMODEL  1024
#define PHYSD   11
#define NTOK    4
#define NHEAD   4
#define DHEAD   256
#define DN      4096
#define LN_EPS  1e-5f

// ---------------- device scratch (allocation-free rule) ----------------
__device__ __half g_h      [(size_t)BATCH * DN];
__device__ float  g_physkv [(size_t)BATCH * DN];
__device__ __half g_kvln   [(size_t)BATCH * DN];
__device__ __half g_qln    [(size_t)BATCH * DMODEL];
__device__ __half g_qproj  [(size_t)BATCH * DMODEL];
__device__ __half g_k      [(size_t)BATCH * DN];
__device__ __half g_v      [(size_t)BATCH * DN];
__device__ __half g_ctx    [(size_t)BATCH * DMODEL];
__device__ float  g_fused  [(size_t)BATCH * DMODEL];
__device__ __half g_fusedln[(size_t)BATCH * DMODEL];
__device__ __half g_ffh    [(size_t)BATCH * 2048];
// transposed weights [N][K] in fp16
__device__ __half g_wt_pw2 [(size_t)DN * DN];
__device__ __half g_wt_q   [(size_t)DMODEL * DMODEL];
__device__ __half g_wt_k   [(size_t)DMODEL * DMODEL];
__device__ __half g_wt_v   [(size_t)DMODEL * DMODEL];
__device__ __half g_wt_o   [(size_t)DMODEL * DMODEL];
__device__ __half g_wt_f1  [(size_t)2048 * DMODEL];
__device__ __half g_wt_f2  [(size_t)DMODEL * 2048];

// ---------------- helpers ----------------
__device__ __forceinline__ float gelu_f(float x) {
    float x3 = x * x * x;
    float t  = tanhf(0.79788456080286535588f * (x + 0.044715f * x3));
    return 0.5f * x * (1.0f + t);
}
__device__ __forceinline__ void cpa16(uint32_t sdst, const void* gsrc) {
    asm volatile("cp.async.cg.shared.global [%0], [%1], 16;\n" :: "r"(sdst), "l"(gsrc));
}

// ================= fp16 GEMM: out[M,N] = A[M,K] @ Wt[N,K]^T + bias =================
// BM=128 BN=256 BK=32, 256 threads = 8 warps (2M x 4N), warp tile 64x64.
// mma.sync.aligned.m16n8k16.row.col.f32.f16.f16.f32, 4-stage cp.async pipeline.
enum { EPI_F32 = 0, EPI_HALF = 1, EPI_FUSED = 2, EPI_GELU_H = 3, EPI_ADDOUT = 4 };

#define LDK        40                         // halves per smem row (pad)
#define A_BYTES    (128 * LDK * 2)            // 10240
#define B_BYTES    (256 * LDK * 2)            // 20480
#define STAGE_B    (A_BYTES + B_BYTES)        // 30720
#define NSTAGE     4
#define SMEM_TOT   (STAGE_B * NSTAGE)         // 122880

template <int EPI>
__global__ __launch_bounds__(256, 1)
void gemm_h(const __half* __restrict__ A, const __half* __restrict__ Wt,
            const float* __restrict__ bias, void* __restrict__ outp,
            const float* __restrict__ aux, const float* __restrict__ gatep,
            int M, int N, int K)
{
    extern __shared__ char smem[];
    const uint32_t sb = (uint32_t)__cvta_generic_to_shared(smem);

    const int tid  = threadIdx.x;
    const int lane = tid & 31;
    const int wid  = tid >> 5;
    const int wm   = wid >> 2;          // 0..1
    const int wn   = wid & 3;           // 0..3
    const int g    = lane >> 2;         // 0..7
    const int c    = lane & 3;          // 0..3
    const int m0   = blockIdx.y * 128;
    const int n0   = blockIdx.x * 256;

    float acc[4][8][4];
#pragma unroll
    for (int mi = 0; mi < 4; mi++)
#pragma unroll
        for (int ni = 0; ni < 8; ni++)
#pragma unroll
            for (int e = 0; e < 4; e++) acc[mi][ni][e] = 0.f;

    const int nt = K >> 5;

    auto fill = [&](int s, int kt) {
        const uint32_t a0 = sb + (uint32_t)s * STAGE_B;
        const uint32_t b0 = a0 + A_BYTES;
        const __half* Ag = A  + (size_t)m0 * K + kt * 32;
        const __half* Bg = Wt + (size_t)n0 * K + kt * 32;
#pragma unroll
        for (int i = 0; i < 2; i++) {
            int idx = tid + 256 * i;          // 0..511
            int r = idx >> 2, c8 = idx & 3;
            cpa16(a0 + (uint32_t)(r * LDK + c8 * 8) * 2, Ag + (size_t)r * K + c8 * 8);
        }
#pragma unroll
        for (int i = 0; i < 4; i++) {
            int idx = tid + 256 * i;          // 0..1023
            int r = idx >> 2, c8 = idx & 3;
            cpa16(b0 + (uint32_t)(r * LDK + c8 * 8) * 2, Bg + (size_t)r * K + c8 * 8);
        }
        asm volatile("cp.async.commit_group;" ::: "memory");
    };

    // prologue: fill 3 stages (nt >= 3 always here)
    fill(0, 0); fill(1, 1); fill(2, 2);

    for (int kt = 0; kt < nt; kt++) {
        const int rem = nt - 1 - kt;
        if (rem >= 2)      asm volatile("cp.async.wait_group 2;" ::: "memory");
        else if (rem == 1) asm volatile("cp.async.wait_group 1;" ::: "memory");
        else               asm volatile("cp.async.wait_group 0;" ::: "memory");
        __syncthreads();

        if (kt + 3 < nt) fill((kt + 3) & 3, kt + 3);

        const int s = kt & 3;
        const __half2* As2 = (const __half2*)(smem + (size_t)s * STAGE_B);
        const __half2* Bs2 = (const __half2*)(smem + (size_t)s * STAGE_B + A_BYTES);

#pragma unroll
        for (int ks = 0; ks < 2; ks++) {
            uint32_t af[4][4];
#pragma unroll
            for (int mi = 0; mi < 4; mi++) {
                int r = wm * 64 + mi * 16 + g;
                af[mi][0] = *(const uint32_t*)&As2[(size_t)r * 20 + ks * 8 + c];
                af[mi][1] = *(const uint32_t*)&As2[(size_t)(r + 8) * 20 + ks * 8 + c];
                af[mi][2] = *(const uint32_t*)&As2[(size_t)r * 20 + ks * 8 + c + 4];
                af[mi][3] = *(const uint32_t*)&As2[(size_t)(r + 8) * 20 + ks * 8 + c + 4];
            }
            uint32_t bf[8][2];
#pragma unroll
            for (int ni = 0; ni < 8; ni++) {
                int n = wn * 64 + ni * 8 + g;
                bf[ni][0] = *(const uint32_t*)&Bs2[(size_t)n * 20 + ks * 8 + c];
                bf[ni][1] = *(const uint32_t*)&Bs2[(size_t)n * 20 + ks * 8 + c + 4];
            }
#pragma unroll
            for (int mi = 0; mi < 4; mi++)
#pragma unroll
                for (int ni = 0; ni < 8; ni++) {
                    asm volatile(
                        "mma.sync.aligned.m16n8k16.row.col.f32.f16.f16.f32 "
                        "{%0,%1,%2,%3}, {%4,%5,%6,%7}, {%8,%9}, {%0,%1,%2,%3};\n"
                        : "+f"(acc[mi][ni][0]), "+f"(acc[mi][ni][1]),
                          "+f"(acc[mi][ni][2]), "+f"(acc[mi][ni][3])
                        : "r"(af[mi][0]), "r"(af[mi][1]), "r"(af[mi][2]), "r"(af[mi][3]),
                          "r"(bf[ni][0]), "r"(bf[ni][1]));
                }
        }
        __syncthreads();
    }

    // ---------------- epilogue ----------------
    float sig = 1.f;
    if (EPI == EPI_FUSED) sig = 1.f / (1.f + expf(-gatep[0]));

#pragma unroll
    for (int mi = 0; mi < 4; mi++) {
#pragma unroll
        for (int ni = 0; ni < 8; ni++) {
            const int col = n0 + wn * 64 + ni * 8 + 2 * c;
            const float b0 = bias[col], b1 = bias[col + 1];
#pragma unroll
            for (int half_ = 0; half_ < 2; half_++) {
                const int row = m0 + wm * 64 + mi * 16 + g + half_ * 8;
                const size_t oi = (size_t)row * N + col;
                float v0 = acc[mi][ni][half_ * 2 + 0] + b0;
                float v1 = acc[mi][ni][half_ * 2 + 1] + b1;
                if (EPI == EPI_F32) {
                    *(float2*)((float*)outp + oi) = make_float2(v0, v1);
                } else if (EPI == EPI_HALF) {
                    *(__half2*)((__half*)outp + oi) = __floats2half2_rn(v0, v1);
                } else if (EPI == EPI_FUSED) {
                    float2 a2 = *(const float2*)(aux + oi);
                    *(float2*)((float*)outp + oi) =
                        make_float2(a2.x + sig * v0, a2.y + sig * v1);
                } else if (EPI == EPI_GELU_H) {
                    *(__half2*)((__half*)outp + oi) =
                        __floats2half2_rn(gelu_f(v0), gelu_f(v1));
                } else { // EPI_ADDOUT
                    float2 a2 = *(const float2*)(aux + oi);
                    *(float2*)((float*)outp + oi) = make_float2(a2.x + v0, a2.y + v1);
                }
            }
        }
    }
}

// ================= weight transpose: Wt[n][k] = (half)W[k][n] =================
__global__ __launch_bounds__(256)
void transpose_w(const float* __restrict__ in, __half* __restrict__ out,
                 int rows, int cols)
{
    __shared__ float t[32][33];
    int bx = blockIdx.x * 32;   // input col tile
    int by = blockIdx.y * 32;   // input row tile
    int x = threadIdx.x, y = threadIdx.y;
#pragma unroll
    for (int j = 0; j < 32; j += 8)
        t[y + j][x] = in[(size_t)(by + y + j) * cols + bx + x];
    __syncthreads();
#pragma unroll
    for (int j = 0; j < 32; j += 8)
        out[(size_t)(bx + y + j) * rows + by + x] = __float2half_rn(t[x][y + j]);
}

// ================= phys MLP stage 1 =================
__global__ __launch_bounds__(256)
void phys_mlp1(const float* __restrict__ phys, const float* __restrict__ pw1,
               const float* __restrict__ pb1, __half* __restrict__ out)
{
    __shared__ float p[PHYSD];
    int b = blockIdx.x;
    int tid = threadIdx.x;
    if (tid < PHYSD) p[tid] = phys[(size_t)b * PHYSD + tid];
    __syncthreads();
    float pr[PHYSD];
#pragma unroll
    for (int k = 0; k < PHYSD; k++) pr[k] = p[k];
    for (int n = tid; n < DN; n += 256) {
        float s = pb1[n];
#pragma unroll
        for (int k = 0; k < PHYSD; k++) s = fmaf(pr[k], pw1[(size_t)k * DN + n], s);
        out[(size_t)b * DN + n] = __float2half_rn(gelu_f(s));
    }
}

// ================= LayerNorm (D=1024) fp32 -> fp16 =================
__global__ __launch_bounds__(256)
void ln1024(const float* __restrict__ x, const float* __restrict__ gg,
            const float* __restrict__ bb, __half* __restrict__ out)
{
    __shared__ float red1[8], red2[8];
    int row = blockIdx.x;
    int tid = threadIdx.x;
    int lane = tid & 31, wid = tid >> 5;

    float4 v = *(const float4*)(x + (size_t)row * DMODEL + tid * 4);
    float s1 = v.x + v.y + v.z + v.w;
    float s2 = v.x * v.x + v.y * v.y + v.z * v.z + v.w * v.w;
#pragma unroll
    for (int o = 16; o > 0; o >>= 1) {
        s1 += __shfl_down_sync(0xFFFFFFFFu, s1, o);
        s2 += __shfl_down_sync(0xFFFFFFFFu, s2, o);
    }
    if (lane == 0) { red1[wid] = s1; red2[wid] = s2; }
    __syncthreads();
    if (tid == 0) {
        float a = 0.f, b2 = 0.f;
#pragma unroll
        for (int i = 0; i < 8; i++) { a += red1[i]; b2 += red2[i]; }
        red1[0] = a; red2[0] = b2;
    }
    __syncthreads();
    float mu  = red1[0] * (1.f / DMODEL);
    float var = red2[0] * (1.f / DMODEL) - mu * mu;
    float rs  = rsqrtf(var + LN_EPS);

    float4 gv = *(const float4*)(gg + tid * 4);
    float4 bv = *(const float4*)(bb + tid * 4);
    __half2 o0 = __floats2half2_rn((v.x - mu) * rs * gv.x + bv.x,
                                   (v.y - mu) * rs * gv.y + bv.y);
    __half2 o1 = __floats2half2_rn((v.z - mu) * rs * gv.z + bv.z,
                                   (v.w - mu) * rs * gv.w + bv.w);
    uint2 pk = make_uint2(*(uint32_t*)&o0, *(uint32_t*)&o1);
    *(uint2*)(out + (size_t)row * DMODEL + tid * 4) = pk;
}

// ================= attention: warp per (b, head), fp16 in/out =================
__device__ __forceinline__ float dot8h(uint4 a, uint4 b) {
    const __half2* pa = (const __half2*)&a;
    const __half2* pb = (const __half2*)&b;
    float s = 0.f;
#pragma unroll
    for (int i = 0; i < 4; i++) {
        float2 fa = __half22float2(pa[i]);
        float2 fb = __half22float2(pb[i]);
        s = fmaf(fa.x, fb.x, s);
        s = fmaf(fa.y, fb.y, s);
    }
    return s;
}

__global__ __launch_bounds__(256)
void attn_kernel(const __half* __restrict__ q, const __half* __restrict__ k,
                 const __half* __restrict__ v, __half* __restrict__ ctx)
{
    int warp = (blockIdx.x * 256 + threadIdx.x) >> 5;
    int lane = threadIdx.x & 31;
    int b = warp >> 2, h = warp & 3;

    size_t qoff = (size_t)b * DMODEL + h * DHEAD;
    uint4 qv = *(const uint4*)(q + qoff + lane * 8);

    float s[NTOK];
#pragma unroll
    for (int t = 0; t < NTOK; t++) {
        size_t koff = (size_t)(b * NTOK + t) * DMODEL + h * DHEAD;
        uint4 kv = *(const uint4*)(k + koff + lane * 8);
        float d = dot8h(qv, kv);
#pragma unroll
        for (int o = 16; o > 0; o >>= 1) d += __shfl_xor_sync(0xFFFFFFFFu, d, o);
        s[t] = d * (1.f / 16.f);   // 1/sqrt(256)
    }
    float m = fmaxf(fmaxf(s[0], s[1]), fmaxf(s[2], s[3]));
    float e[NTOK], sum = 0.f;
#pragma unroll
    for (int t = 0; t < NTOK; t++) { e[t] = expf(s[t] - m); sum += e[t]; }
    float inv = 1.f / sum;

    float cacc[8];
#pragma unroll
    for (int i = 0; i < 8; i++) cacc[i] = 0.f;
#pragma unroll
    for (int t = 0; t < NTOK; t++) {
        float a = e[t] * inv;
        size_t voff = (size_t)(b * NTOK + t) * DMODEL + h * DHEAD;
        uint4 vv = *(const uint4*)(v + voff + lane * 8);
        const __half2* pv = (const __half2*)&vv;
#pragma unroll
        for (int i = 0; i < 4; i++) {
            float2 f = __half22float2(pv[i]);
            cacc[2 * i]     = fmaf(a, f.x, cacc[2 * i]);
            cacc[2 * i + 1] = fmaf(a, f.y, cacc[2 * i + 1]);
        }
    }
    uint4 ov;
    __half2* po = (__half2*)&ov;
#pragma unroll
    for (int i = 0; i < 4; i++)
        po[i] = __floats2half2_rn(cacc[2 * i], cacc[2 * i + 1]);
    *(uint4*)(ctx + qoff + lane * 8) = ov;
}

// ================= host launcher =================
extern "C" void kernel_launch(void* const* d_in, const int* in_sizes, int n_in,
                              void* d_out, int out_size)
{
    const float* embedding = (const float*)d_in[0];
    const float* physics   = (const float*)d_in[1];
    const float* pw1   = (const float*)d_in[2];
    const float* pb1   = (const float*)d_in[3];
    const float* pw2   = (const float*)d_in[4];
    const float* pb2   = (const float*)d_in[5];
    const float* lnq_g = (const float*)d_in[6];
    const float* lnq_b = (const float*)d_in[7];
    const float* lnkv_g = (const float*)d_in[8];
    const float* lnkv_b = (const float*)d_in[9];
    const float* wq = (const float*)d_in[10];
    const float* bq = (const float*)d_in[11];
    const float* wk = (const float*)d_in[12];
    const float* bk = (const float*)d_in[13];
    const float* wv = (const float*)d_in[14];
    const float* bv = (const float*)d_in[15];
    const float* wo = (const float*)d_in[16];
    const float* bo = (const float*)d_in[17];
    const float* ffn_g = (const float*)d_in[18];
    const float* ffn_b = (const float*)d_in[19];
    const float* fw1 = (const float*)d_in[20];
    const float* fb1 = (const float*)d_in[21];
    const float* fw2 = (const float*)d_in[22];
    const float* fb2 = (const float*)d_in[23];
    const float* gate = (const float*)d_in[24];
    float* out = (float*)d_out;

    __half *p_h, *p_kvln, *p_qln, *p_qproj, *p_k, *p_v, *p_ctx, *p_fusedln, *p_ffh;
    __half *wt_pw2, *wt_q, *wt_k, *wt_v, *wt_o, *wt_f1, *wt_f2;
    float  *p_physkv, *p_fused;
    cudaGetSymbolAddress((void**)&p_h, g_h);
    cudaGetSymbolAddress((void**)&p_physkv, g_physkv);
    cudaGetSymbolAddress((void**)&p_kvln, g_kvln);
    cudaGetSymbolAddress((void**)&p_qln, g_qln);
    cudaGetSymbolAddress((void**)&p_qproj, g_qproj);
    cudaGetSymbolAddress((void**)&p_k, g_k);
    cudaGetSymbolAddress((void**)&p_v, g_v);
    cudaGetSymbolAddress((void**)&p_ctx, g_ctx);
    cudaGetSymbolAddress((void**)&p_fused, g_fused);
    cudaGetSymbolAddress((void**)&p_fusedln, g_fusedln);
    cudaGetSymbolAddress((void**)&p_ffh, g_ffh);
    cudaGetSymbolAddress((void**)&wt_pw2, g_wt_pw2);
    cudaGetSymbolAddress((void**)&wt_q, g_wt_q);
    cudaGetSymbolAddress((void**)&wt_k, g_wt_k);
    cudaGetSymbolAddress((void**)&wt_v, g_wt_v);
    cudaGetSymbolAddress((void**)&wt_o, g_wt_o);
    cudaGetSymbolAddress((void**)&wt_f1, g_wt_f1);
    cudaGetSymbolAddress((void**)&wt_f2, g_wt_f2);

    cudaFuncSetAttribute(gemm_h<EPI_F32>,    cudaFuncAttributeMaxDynamicSharedMemorySize, SMEM_TOT);
    cudaFuncSetAttribute(gemm_h<EPI_HALF>,   cudaFuncAttributeMaxDynamicSharedMemorySize, SMEM_TOT);
    cudaFuncSetAttribute(gemm_h<EPI_FUSED>,  cudaFuncAttributeMaxDynamicSharedMemorySize, SMEM_TOT);
    cudaFuncSetAttribute(gemm_h<EPI_GELU_H>, cudaFuncAttributeMaxDynamicSharedMemorySize, SMEM_TOT);
    cudaFuncSetAttribute(gemm_h<EPI_ADDOUT>, cudaFuncAttributeMaxDynamicSharedMemorySize, SMEM_TOT);

    dim3 tb(32, 8);
    transpose_w<<<dim3(DN / 32, DN / 32), tb>>>(pw2, wt_pw2, DN, DN);
    transpose_w<<<dim3(DMODEL / 32, DMODEL / 32), tb>>>(wq, wt_q, DMODEL, DMODEL);
    transpose_w<<<dim3(DMODEL / 32, DMODEL / 32), tb>>>(wk, wt_k, DMODEL, DMODEL);
    transpose_w<<<dim3(DMODEL / 32, DMODEL / 32), tb>>>(wv, wt_v, DMODEL, DMODEL);
    transpose_w<<<dim3(DMODEL / 32, DMODEL / 32), tb>>>(wo, wt_o, DMODEL, DMODEL);
    transpose_w<<<dim3(2048 / 32, DMODEL / 32), tb>>>(fw1, wt_f1, DMODEL, 2048);
    transpose_w<<<dim3(DMODEL / 32, 2048 / 32), tb>>>(fw2, wt_f2, 2048, DMODEL);

    // 1) h = gelu(physics @ pw1 + pb1)  -> fp16
    phys_mlp1<<<BATCH, 256>>>(physics, pw1, pb1, p_h);

    // 2) physkv = h @ pw2 + pb2  (fp32 out, feeds LN)
    gemm_h<EPI_F32><<<dim3(DN / 256, BATCH / 128), 256, SMEM_TOT>>>(
        p_h, wt_pw2, pb2, p_physkv, nullptr, nullptr, BATCH, DN, DN);

    // 3) LayerNorms -> fp16
    ln1024<<<BATCH * NTOK, 256>>>(p_physkv, lnkv_g, lnkv_b, p_kvln);
    ln1024<<<BATCH, 256>>>(embedding, lnq_g, lnq_b, p_qln);

    // 4) q/k/v projections -> fp16
    gemm_h<EPI_HALF><<<dim3(DMODEL / 256, BATCH / 128), 256, SMEM_TOT>>>(
        p_qln, wt_q, bq, p_qproj, nullptr, nullptr, BATCH, DMODEL, DMODEL);
    gemm_h<EPI_HALF><<<dim3(DMODEL / 256, (BATCH * NTOK) / 128), 256, SMEM_TOT>>>(
        p_kvln, wt_k, bk, p_k, nullptr, nullptr, BATCH * NTOK, DMODEL, DMODEL);
    gemm_h<EPI_HALF><<<dim3(DMODEL / 256, (BATCH * NTOK) / 128), 256, SMEM_TOT>>>(
        p_kvln, wt_v, bv, p_v, nullptr, nullptr, BATCH * NTOK, DMODEL, DMODEL);

    // 5) attention -> ctx fp16
    attn_kernel<<<(BATCH * NHEAD) / 8, 256>>>(p_qproj, p_k, p_v, p_ctx);

    // 6) fused = embedding + sigmoid(gate) * (ctx @ wo + bo)  (fp32)
    gemm_h<EPI_FUSED><<<dim3(DMODEL / 256, BATCH / 128), 256, SMEM_TOT>>>(
        p_ctx, wt_o, bo, p_fused, embedding, gate, BATCH, DMODEL, DMODEL);

    // 7) LN(fused) -> fp16
    ln1024<<<BATCH, 256>>>(p_fused, ffn_g, ffn_b, p_fusedln);

    // 8) ffh = gelu(fusedln @ fw1 + fb1) -> fp16
    gemm_h<EPI_GELU_H><<<dim3(2048 / 256, BATCH / 128), 256, SMEM_TOT>>>(
        p_fusedln, wt_f1, fb1, p_ffh, nullptr, nullptr, BATCH, 2048, DMODEL);

    // 9) out = fused + ffh @ fw2 + fb2  (fp32)
    gemm_h<EPI_ADDOUT><<<dim3(DMODEL / 256, BATCH / 128), 256, SMEM_TOT>>>(
        p_ffh, wt_f2, fb2, out, p_fused, nullptr, BATCH, DMODEL, 2048);
}

// round 7
// speedup vs baseline: 2.1752x; 1.0479x over previous
#include <cuda_runtime.h>
#include <cuda_fp16.h>
#include <cstdint>
#include <cstddef>

// ---------------- problem constants ----------------
#define BATCH   16384
#define DMODEL  1024
#define PHYSD   11
#define NTOK    4
#define NHEAD   4
#define DHEAD   256
#define DN      4096
#define LN_EPS  1e-5f

// ---------------- device scratch (allocation-free rule) ----------------
__device__ __half g_h      [(size_t)BATCH * DN];
__device__ float  g_physkv [(size_t)BATCH * DN];
__device__ __half g_kvln   [(size_t)BATCH * DN];
__device__ __half g_qln    [(size_t)BATCH * DMODEL];
__device__ __half g_qproj  [(size_t)BATCH * DMODEL];
__device__ __half g_kv     [(size_t)BATCH * NTOK * 2048];   // [k(1024) | v(1024)] per token
__device__ __half g_ctx    [(size_t)BATCH * DMODEL];
__device__ float  g_fused  [(size_t)BATCH * DMODEL];
__device__ __half g_fusedln[(size_t)BATCH * DMODEL];
__device__ __half g_ffh    [(size_t)BATCH * 2048];
// transposed weights [N][K] fp16
__device__ __half g_wt_pw2 [(size_t)DN * DN];
__device__ __half g_wt_q   [(size_t)DMODEL * DMODEL];
__device__ __half g_wt_kv  [(size_t)2048 * DMODEL];
__device__ __half g_wt_o   [(size_t)DMODEL * DMODEL];
__device__ __half g_wt_f1  [(size_t)2048 * DMODEL];
__device__ __half g_wt_f2  [(size_t)DMODEL * 2048];
__device__ float  g_b_kv   [2048];

// ---------------- helpers ----------------
__device__ __forceinline__ float gelu_f(float x) {
    float x3 = x * x * x;
    float t  = tanhf(0.79788456080286535588f * (x + 0.044715f * x3));
    return 0.5f * x * (1.0f + t);
}
__device__ __forceinline__ void cpa16(uint32_t sdst, const void* gsrc) {
    asm volatile("cp.async.cg.shared.global [%0], [%1], 16;\n" :: "r"(sdst), "l"(gsrc));
}
__device__ __forceinline__ void ldsm4(uint32_t& r0, uint32_t& r1, uint32_t& r2, uint32_t& r3,
                                      uint32_t addr) {
    asm volatile("ldmatrix.sync.aligned.m8n8.x4.shared.b16 {%0,%1,%2,%3}, [%4];"
                 : "=r"(r0), "=r"(r1), "=r"(r2), "=r"(r3) : "r"(addr));
}

// ================= fp16 GEMM: out[M,N] = A[M,K] @ Wt[N,K]^T + bias =================
// BM=128 BN=256 BK=32, 256 threads = 8 warps (2M x 4N), warp tile 64x64.
// ldmatrix fragment loads, 4-stage cp.async pipeline, 1 barrier per k-tile.
enum { EPI_F32 = 0, EPI_HALF = 1, EPI_FUSED = 2, EPI_GELU_H = 3, EPI_ADDOUT = 4 };

#define LDK        40                         // halves per smem row (pad)
#define A_BYTES    (128 * LDK * 2)            // 10240
#define B_BYTES    (256 * LDK * 2)            // 20480
#define STAGE_B    (A_BYTES + B_BYTES)        // 30720
#define NSTAGE     4
#define SMEM_TOT   (STAGE_B * NSTAGE)         // 122880

template <int EPI>
__global__ __launch_bounds__(256, 1)
void gemm_h(const __half* __restrict__ A, const __half* __restrict__ Wt,
            const float* __restrict__ bias, void* __restrict__ outp,
            const float* __restrict__ aux, const float* __restrict__ gatep,
            int M, int N, int K)
{
    extern __shared__ char smem[];
    const uint32_t sb = (uint32_t)__cvta_generic_to_shared(smem);

    const int tid  = threadIdx.x;
    const int lane = tid & 31;
    const int wid  = tid >> 5;
    const int wm   = wid >> 2;          // 0..1
    const int wn   = wid & 3;           // 0..3
    const int g    = lane >> 2;         // 0..7
    const int c    = lane & 3;          // 0..3
    const int m0   = blockIdx.y * 128;
    const int n0   = blockIdx.x * 256;

    // ldmatrix per-lane source coordinates (within the CTA tile)
    const int a_row  = wm * 64 + (lane & 15);       // + mi*16
    const int a_koff = (lane >> 4) << 3;            // 0 or 8
    const int b_row  = wn * 64 + ((lane >> 4) << 3) + (lane & 7);  // + nj*16
    const int b_koff = lane & 8;                    // 0 or 8

    float acc[4][8][4];
#pragma unroll
    for (int mi = 0; mi < 4; mi++)
#pragma unroll
        for (int ni = 0; ni < 8; ni++)
#pragma unroll
            for (int e = 0; e < 4; e++) acc[mi][ni][e] = 0.f;

    const int nt = K >> 5;

    auto fill = [&](int s, int kt) {
        const uint32_t a0 = sb + (uint32_t)s * STAGE_B;
        const uint32_t b0 = a0 + A_BYTES;
        const __half* Ag = A  + (size_t)m0 * K + kt * 32;
        const __half* Bg = Wt + (size_t)n0 * K + kt * 32;
#pragma unroll
        for (int i = 0; i < 2; i++) {
            int idx = tid + 256 * i;
            int r = idx >> 2, c8 = idx & 3;
            cpa16(a0 + (uint32_t)(r * LDK + c8 * 8) * 2, Ag + (size_t)r * K + c8 * 8);
        }
#pragma unroll
        for (int i = 0; i < 4; i++) {
            int idx = tid + 256 * i;
            int r = idx >> 2, c8 = idx & 3;
            cpa16(b0 + (uint32_t)(r * LDK + c8 * 8) * 2, Bg + (size_t)r * K + c8 * 8);
        }
        asm volatile("cp.async.commit_group;" ::: "memory");
    };

    fill(0, 0); fill(1, 1); fill(2, 2);

    for (int kt = 0; kt < nt; kt++) {
        const int rem = nt - 1 - kt;
        if (rem >= 2)      asm volatile("cp.async.wait_group 2;" ::: "memory");
        else if (rem == 1) asm volatile("cp.async.wait_group 1;" ::: "memory");
        else               asm volatile("cp.async.wait_group 0;" ::: "memory");
        __syncthreads();

        if (kt + 3 < nt) fill((kt + 3) & 3, kt + 3);

        const int s = kt & 3;
        const uint32_t aBase = sb + (uint32_t)s * STAGE_B;
        const uint32_t bBase = aBase + A_BYTES;

#pragma unroll
        for (int ks = 0; ks < 2; ks++) {
            const int k0 = ks * 16;
            uint32_t af[4][4];
#pragma unroll
            for (int mi = 0; mi < 4; mi++)
                ldsm4(af[mi][0], af[mi][1], af[mi][2], af[mi][3],
                      aBase + (uint32_t)((a_row + mi * 16) * LDK + k0 + a_koff) * 2);
            uint32_t bf[8][2];
#pragma unroll
            for (int nj = 0; nj < 4; nj++) {
                uint32_t r0, r1, r2, r3;
                ldsm4(r0, r1, r2, r3,
                      bBase + (uint32_t)((b_row + nj * 16) * LDK + k0 + b_koff) * 2);
                bf[2 * nj][0] = r0; bf[2 * nj][1] = r1;
                bf[2 * nj + 1][0] = r2; bf[2 * nj + 1][1] = r3;
            }
#pragma unroll
            for (int mi = 0; mi < 4; mi++)
#pragma unroll
                for (int ni = 0; ni < 8; ni++) {
                    asm volatile(
                        "mma.sync.aligned.m16n8k16.row.col.f32.f16.f16.f32 "
                        "{%0,%1,%2,%3}, {%4,%5,%6,%7}, {%8,%9}, {%0,%1,%2,%3};\n"
                        : "+f"(acc[mi][ni][0]), "+f"(acc[mi][ni][1]),
                          "+f"(acc[mi][ni][2]), "+f"(acc[mi][ni][3])
                        : "r"(af[mi][0]), "r"(af[mi][1]), "r"(af[mi][2]), "r"(af[mi][3]),
                          "r"(bf[ni][0]), "r"(bf[ni][1]));
                }
        }
    }

    // ---------------- epilogue ----------------
    float sig = 1.f;
    if (EPI == EPI_FUSED) sig = 1.f / (1.f + expf(-gatep[0]));

#pragma unroll
    for (int mi = 0; mi < 4; mi++) {
#pragma unroll
        for (int ni = 0; ni < 8; ni++) {
            const int col = n0 + wn * 64 + ni * 8 + 2 * c;
            const float b0 = bias[col], b1 = bias[col + 1];
#pragma unroll
            for (int half_ = 0; half_ < 2; half_++) {
                const int row = m0 + wm * 64 + mi * 16 + g + half_ * 8;
                const size_t oi = (size_t)row * N + col;
                float v0 = acc[mi][ni][half_ * 2 + 0] + b0;
                float v1 = acc[mi][ni][half_ * 2 + 1] + b1;
                if (EPI == EPI_F32) {
                    *(float2*)((float*)outp + oi) = make_float2(v0, v1);
                } else if (EPI == EPI_HALF) {
                    *(__half2*)((__half*)outp + oi) = __floats2half2_rn(v0, v1);
                } else if (EPI == EPI_FUSED) {
                    float2 a2 = *(const float2*)(aux + oi);
                    *(float2*)((float*)outp + oi) =
                        make_float2(a2.x + sig * v0, a2.y + sig * v1);
                } else if (EPI == EPI_GELU_H) {
                    *(__half2*)((__half*)outp + oi) =
                        __floats2half2_rn(gelu_f(v0), gelu_f(v1));
                } else { // EPI_ADDOUT
                    float2 a2 = *(const float2*)(aux + oi);
                    *(float2*)((float*)outp + oi) = make_float2(a2.x + v0, a2.y + v1);
                }
            }
        }
    }
}

// ================= weight transpose: Wt[n][k] = (half)W[k][n] =================
__global__ __launch_bounds__(256)
void transpose_w(const float* __restrict__ in, __half* __restrict__ out,
                 int rows, int cols)
{
    __shared__ float t[32][33];
    int bx = blockIdx.x * 32;
    int by = blockIdx.y * 32;
    int x = threadIdx.x, y = threadIdx.y;
#pragma unroll
    for (int j = 0; j < 32; j += 8)
        t[y + j][x] = in[(size_t)(by + y + j) * cols + bx + x];
    __syncthreads();
#pragma unroll
    for (int j = 0; j < 32; j += 8)
        out[(size_t)(bx + y + j) * rows + by + x] = __float2half_rn(t[x][y + j]);
}

// ================= bias concat =================
__global__ void concat_bias(const float* __restrict__ a, const float* __restrict__ b,
                            float* __restrict__ o)
{
    int i = blockIdx.x * blockDim.x + threadIdx.x;
    o[i] = (i < 1024) ? a[i] : b[i - 1024];
}

// ================= phys MLP stage 1 =================
__global__ __launch_bounds__(256)
void phys_mlp1(const float* __restrict__ phys, const float* __restrict__ pw1,
               const float* __restrict__ pb1, __half* __restrict__ out)
{
    __shared__ float p[PHYSD];
    int b = blockIdx.x;
    int tid = threadIdx.x;
    if (tid < PHYSD) p[tid] = phys[(size_t)b * PHYSD + tid];
    __syncthreads();
    float pr[PHYSD];
#pragma unroll
    for (int k = 0; k < PHYSD; k++) pr[k] = p[k];
    for (int n = tid; n < DN; n += 256) {
        float s = pb1[n];
#pragma unroll
        for (int k = 0; k < PHYSD; k++) s = fmaf(pr[k], pw1[(size_t)k * DN + n], s);
        out[(size_t)b * DN + n] = __float2half_rn(gelu_f(s));
    }
}

// ================= LayerNorm (D=1024) fp32 -> fp16 =================
__global__ __launch_bounds__(256)
void ln1024(const float* __restrict__ x, const float* __restrict__ gg,
            const float* __restrict__ bb, __half* __restrict__ out)
{
    __shared__ float red1[8], red2[8];
    int row = blockIdx.x;
    int tid = threadIdx.x;
    int lane = tid & 31, wid = tid >> 5;

    float4 v = *(const float4*)(x + (size_t)row * DMODEL + tid * 4);
    float s1 = v.x + v.y + v.z + v.w;
    float s2 = v.x * v.x + v.y * v.y + v.z * v.z + v.w * v.w;
#pragma unroll
    for (int o = 16; o > 0; o >>= 1) {
        s1 += __shfl_down_sync(0xFFFFFFFFu, s1, o);
        s2 += __shfl_down_sync(0xFFFFFFFFu, s2, o);
    }
    if (lane == 0) { red1[wid] = s1; red2[wid] = s2; }
    __syncthreads();
    if (tid == 0) {
        float a = 0.f, b2 = 0.f;
#pragma unroll
        for (int i = 0; i < 8; i++) { a += red1[i]; b2 += red2[i]; }
        red1[0] = a; red2[0] = b2;
    }
    __syncthreads();
    float mu  = red1[0] * (1.f / DMODEL);
    float var = red2[0] * (1.f / DMODEL) - mu * mu;
    float rs  = rsqrtf(var + LN_EPS);

    float4 gv = *(const float4*)(gg + tid * 4);
    float4 bv = *(const float4*)(bb + tid * 4);
    __half2 o0 = __floats2half2_rn((v.x - mu) * rs * gv.x + bv.x,
                                   (v.y - mu) * rs * gv.y + bv.y);
    __half2 o1 = __floats2half2_rn((v.z - mu) * rs * gv.z + bv.z,
                                   (v.w - mu) * rs * gv.w + bv.w);
    uint2 pk = make_uint2(*(uint32_t*)&o0, *(uint32_t*)&o1);
    *(uint2*)(out + (size_t)row * DMODEL + tid * 4) = pk;
}

// ================= attention: warp per (b, head), packed kv =================
__device__ __forceinline__ float dot8h(uint4 a, uint4 b) {
    const __half2* pa = (const __half2*)&a;
    const __half2* pb = (const __half2*)&b;
    float s = 0.f;
#pragma unroll
    for (int i = 0; i < 4; i++) {
        float2 fa = __half22float2(pa[i]);
        float2 fb = __half22float2(pb[i]);
        s = fmaf(fa.x, fb.x, s);
        s = fmaf(fa.y, fb.y, s);
    }
    return s;
}

__global__ __launch_bounds__(256)
void attn_kernel(const __half* __restrict__ q, const __half* __restrict__ kv,
                 __half* __restrict__ ctx)
{
    int warp = (blockIdx.x * 256 + threadIdx.x) >> 5;
    int lane = threadIdx.x & 31;
    int b = warp >> 2, h = warp & 3;

    size_t qoff = (size_t)b * DMODEL + h * DHEAD;
    uint4 qv = *(const uint4*)(q + qoff + lane * 8);

    float s[NTOK];
#pragma unroll
    for (int t = 0; t < NTOK; t++) {
        size_t koff = (size_t)(b * NTOK + t) * 2048 + h * DHEAD;
        uint4 kvec = *(const uint4*)(kv + koff + lane * 8);
        float d = dot8h(qv, kvec);
#pragma unroll
        for (int o = 16; o > 0; o >>= 1) d += __shfl_xor_sync(0xFFFFFFFFu, d, o);
        s[t] = d * (1.f / 16.f);   // 1/sqrt(256)
    }
    float m = fmaxf(fmaxf(s[0], s[1]), fmaxf(s[2], s[3]));
    float e[NTOK], sum = 0.f;
#pragma unroll
    for (int t = 0; t < NTOK; t++) { e[t] = expf(s[t] - m); sum += e[t]; }
    float inv = 1.f / sum;

    float cacc[8];
#pragma unroll
    for (int i = 0; i < 8; i++) cacc[i] = 0.f;
#pragma unroll
    for (int t = 0; t < NTOK; t++) {
        float a = e[t] * inv;
        size_t voff = (size_t)(b * NTOK + t) * 2048 + 1024 + h * DHEAD;
        uint4 vv = *(const uint4*)(kv + voff + lane * 8);
        const __half2* pv = (const __half2*)&vv;
#pragma unroll
        for (int i = 0; i < 4; i++) {
            float2 f = __half22float2(pv[i]);
            cacc[2 * i]     = fmaf(a, f.x, cacc[2 * i]);
            cacc[2 * i + 1] = fmaf(a, f.y, cacc[2 * i + 1]);
        }
    }
    uint4 ov;
    __half2* po = (__half2*)&ov;
#pragma unroll
    for (int i = 0; i < 4; i++)
        po[i] = __floats2half2_rn(cacc[2 * i], cacc[2 * i + 1]);
    *(uint4*)(ctx + qoff + lane * 8) = ov;
}

// ================= host launcher =================
extern "C" void kernel_launch(void* const* d_in, const int* in_sizes, int n_in,
                              void* d_out, int out_size)
{
    const float* embedding = (const float*)d_in[0];
    const float* physics   = (const float*)d_in[1];
    const float* pw1   = (const float*)d_in[2];
    const float* pb1   = (const float*)d_in[3];
    const float* pw2   = (const float*)d_in[4];
    const float* pb2   = (const float*)d_in[5];
    const float* lnq_g = (const float*)d_in[6];
    const float* lnq_b = (const float*)d_in[7];
    const float* lnkv_g = (const float*)d_in[8];
    const float* lnkv_b = (const float*)d_in[9];
    const float* wq = (const float*)d_in[10];
    const float* bq = (const float*)d_in[11];
    const float* wk = (const float*)d_in[12];
    const float* bk = (const float*)d_in[13];
    const float* wv = (const float*)d_in[14];
    const float* bv = (const float*)d_in[15];
    const float* wo = (const float*)d_in[16];
    const float* bo = (const float*)d_in[17];
    const float* ffn_g = (const float*)d_in[18];
    const float* ffn_b = (const float*)d_in[19];
    const float* fw1 = (const float*)d_in[20];
    const float* fb1 = (const float*)d_in[21];
    const float* fw2 = (const float*)d_in[22];
    const float* fb2 = (const float*)d_in[23];
    const float* gate = (const float*)d_in[24];
    float* out = (float*)d_out;

    __half *p_h, *p_kvln, *p_qln, *p_qproj, *p_kv, *p_ctx, *p_fusedln, *p_ffh;
    __half *wt_pw2, *wt_q, *wt_kv, *wt_o, *wt_f1, *wt_f2;
    float  *p_physkv, *p_fused, *p_bkv;
    cudaGetSymbolAddress((void**)&p_h, g_h);
    cudaGetSymbolAddress((void**)&p_physkv, g_physkv);
    cudaGetSymbolAddress((void**)&p_kvln, g_kvln);
    cudaGetSymbolAddress((void**)&p_qln, g_qln);
    cudaGetSymbolAddress((void**)&p_qproj, g_qproj);
    cudaGetSymbolAddress((void**)&p_kv, g_kv);
    cudaGetSymbolAddress((void**)&p_ctx, g_ctx);
    cudaGetSymbolAddress((void**)&p_fused, g_fused);
    cudaGetSymbolAddress((void**)&p_fusedln, g_fusedln);
    cudaGetSymbolAddress((void**)&p_ffh, g_ffh);
    cudaGetSymbolAddress((void**)&wt_pw2, g_wt_pw2);
    cudaGetSymbolAddress((void**)&wt_q, g_wt_q);
    cudaGetSymbolAddress((void**)&wt_kv, g_wt_kv);
    cudaGetSymbolAddress((void**)&wt_o, g_wt_o);
    cudaGetSymbolAddress((void**)&wt_f1, g_wt_f1);
    cudaGetSymbolAddress((void**)&wt_f2, g_wt_f2);
    cudaGetSymbolAddress((void**)&p_bkv, g_b_kv);

    cudaFuncSetAttribute(gemm_h<EPI_F32>,    cudaFuncAttributeMaxDynamicSharedMemorySize, SMEM_TOT);
    cudaFuncSetAttribute(gemm_h<EPI_HALF>,   cudaFuncAttributeMaxDynamicSharedMemorySize, SMEM_TOT);
    cudaFuncSetAttribute(gemm_h<EPI_FUSED>,  cudaFuncAttributeMaxDynamicSharedMemorySize, SMEM_TOT);
    cudaFuncSetAttribute(gemm_h<EPI_GELU_H>, cudaFuncAttributeMaxDynamicSharedMemorySize, SMEM_TOT);
    cudaFuncSetAttribute(gemm_h<EPI_ADDOUT>, cudaFuncAttributeMaxDynamicSharedMemorySize, SMEM_TOT);

    dim3 tb(32, 8);
    // launches 1-5 (ncu -s 5 -c 1 profiles launch #6 = the big GEMM)
    transpose_w<<<dim3(DN / 32, DN / 32), tb>>>(pw2, wt_pw2, DN, DN);               // 1
    phys_mlp1<<<BATCH, 256>>>(physics, pw1, pb1, p_h);                              // 2
    transpose_w<<<dim3(DMODEL / 32, DMODEL / 32), tb>>>(wq, wt_q, DMODEL, DMODEL);  // 3
    transpose_w<<<dim3(DMODEL / 32, DMODEL / 32), tb>>>(wk, wt_kv, DMODEL, DMODEL); // 4
    transpose_w<<<dim3(DMODEL / 32, DMODEL / 32), tb>>>(
        wv, wt_kv + (size_t)DMODEL * DMODEL, DMODEL, DMODEL);                       // 5

    // 6) BIG GEMM: physkv = h @ pw2 + pb2  (fp32 out, feeds LN)  [PROFILED]
    gemm_h<EPI_F32><<<dim3(DN / 256, BATCH / 128), 256, SMEM_TOT>>>(
        p_h, wt_pw2, pb2, p_physkv, nullptr, nullptr, BATCH, DN, DN);

    // remaining weight prep
    transpose_w<<<dim3(DMODEL / 32, DMODEL / 32), tb>>>(wo, wt_o, DMODEL, DMODEL);
    transpose_w<<<dim3(2048 / 32, DMODEL / 32), tb>>>(fw1, wt_f1, DMODEL, 2048);
    transpose_w<<<dim3(DMODEL / 32, 2048 / 32), tb>>>(fw2, wt_f2, 2048, DMODEL);
    concat_bias<<<2, 1024>>>(bk, bv, p_bkv);

    // LayerNorms -> fp16
    ln1024<<<BATCH * NTOK, 256>>>(p_physkv, lnkv_g, lnkv_b, p_kvln);
    ln1024<<<BATCH, 256>>>(embedding, lnq_g, lnq_b, p_qln);

    // projections
    gemm_h<EPI_HALF><<<dim3(DMODEL / 256, BATCH / 128), 256, SMEM_TOT>>>(
        p_qln, wt_q, bq, p_qproj, nullptr, nullptr, BATCH, DMODEL, DMODEL);
    gemm_h<EPI_HALF><<<dim3(2048 / 256, (BATCH * NTOK) / 128), 256, SMEM_TOT>>>(
        p_kvln, wt_kv, p_bkv, p_kv, nullptr, nullptr, BATCH * NTOK, 2048, DMODEL);

    // attention
    attn_kernel<<<(BATCH * NHEAD) / 8, 256>>>(p_qproj, p_kv, p_ctx);

    // fused = embedding + sigmoid(gate) * (ctx @ wo + bo)  (fp32)
    gemm_h<EPI_FUSED><<<dim3(DMODEL / 256, BATCH / 128), 256, SMEM_TOT>>>(
        p_ctx, wt_o, bo, p_fused, embedding, gate, BATCH, DMODEL, DMODEL);

    // LN(fused) -> fp16
    ln1024<<<BATCH, 256>>>(p_fused, ffn_g, ffn_b, p_fusedln);

    // ffh = gelu(fusedln @ fw1 + fb1) -> fp16
    gemm_h<EPI_GELU_H><<<dim3(2048 / 256, BATCH / 128), 256, SMEM_TOT>>>(
        p_fusedln, wt_f1, fb1, p_ffh, nullptr, nullptr, BATCH, 2048, DMODEL);

    // out = fused + ffh @ fw2 + fb2  (fp32)
    gemm_h<EPI_ADDOUT><<<dim3(DMODEL / 256, BATCH / 128), 256, SMEM_TOT>>>(
        p_ffh, wt_f2, fb2, out, p_fused, nullptr, BATCH, DMODEL, 2048);
}